// round 10
// baseline (speedup 1.0000x reference)
#include <cuda_runtime.h>
#include <cuda_bf16.h>

// Problem constants (fixed by the reference: B=4096, N=256, K=16)
#define NN    256
#define KK    16
#define PP    32640            // N*(N-1)/2
#define BB    4096
#define TPB   256              // threads per block
#define NG    2                // groups of 4 consecutive pairs per thread
#define TILE  (TPB * NG * 4)   // 2048 pairs per block tile
#define GX    16               // p-tiles: 16*2048 = 32768 >= 32640
#define GY    128              // each block owns 32 CONTIGUOUS batch rows
#define ROWSB 32               // rows per block
#define RST   4                // rows staged per barrier round
#define CS    256              // floats per shift copy

// pstart(i) = number of pairs before row i = i*(N-1) - i*(i-1)/2
__host__ __device__ __forceinline__ int pstart(int i) {
    return i * (NN - 1) - (i * (i - 1)) / 2;
}

// invert triangular index p -> (i, j)
__device__ __forceinline__ void inv_tri(int pc, int& io, int& jo) {
    float disc = 2.0f * NN - 1.0f;       // 511
    int i = (int)floorf((disc - sqrtf(disc * disc - 8.0f * (float)pc)) * 0.5f);
    if (i < 0) i = 0;
    if (i > NN - 2) i = NN - 2;
    while (i < NN - 2 && pstart(i + 1) <= pc) i++;
    while (i > 0 && pstart(i) > pc) i--;
    io = i;
    jo = i + 1 + (pc - pstart(i));
}

// ---------------------------------------------------------------------------
// Main kernel: all groups whose 4 pairs lie in ONE row i (97% of groups).
// Branch-free hot loop: 1 LDS.32 + 1 LDS.128 + 1 predicated STG.128 per group.
// ---------------------------------------------------------------------------
__global__ void __launch_bounds__(TPB)
cross_utpm_main(const float* __restrict__ x,
                const float* __restrict__ L,
                float* __restrict__ out)
{
    // S[row-in-stage][copy r][pos m] = x[b, m + r]; flat: row*4*CS + r*CS + m
    __shared__ __align__(16) float S[RST * 4 * CS];

    const int t  = threadIdx.x;
    const int p0 = blockIdx.x * TILE;
    const int bbase = blockIdx.y * ROWSB;

    // ---- one-time per-thread setup (b-invariant) ----
    int   offA[NG];      // flat offset (within one row's 4-copy region) of xj LDS.128
    int   offI[NG];      // flat offset of xi (copy 0)
    int   poff[NG];      // output offset within the p-row
    float sp[NG][4];
    bool  pred[NG];      // store enabled: group valid AND single-row

#pragma unroll
    for (int g = 0; g < NG; g++) {
        int pg = p0 + (g * TPB + t) * 4;
        bool valid = (pg < PP);
        int base = valid ? pg : 0;

        int i0, j0, i3, j3;
        inv_tri(base,     i0, j0);
        inv_tri(base + 3, i3, j3);
        pred[g] = valid && (i0 == i3);      // uniform group only

        poff[g] = base;
        offI[g] = i0;                        // copy 0 scalar
        int rA  = j0 & 3;
        offA[g] = rA * CS + (j0 - rA);       // 16B aligned within copy rA

#pragma unroll
        for (int k = 0; k < 4; k++) {
            int i, j;
            inv_tri(base + k, i, j);
            float s = 0.0f;
#pragma unroll
            for (int kk = 0; kk < KK; kk++)
                s += L[i * KK + kk] * L[j * KK + kk];
            sp[g][k] = s;
        }
    }

    // ---- loop over this block's 32 contiguous rows, staged 4 at a time ----
    const int t6 = t & 63;          // position group within a row (64 float4s)
    const int rr_fill = t >> 6;     // which of the 4 staged rows this thread fills

    for (int s = 0; s < ROWSB; s += RST) {
        int b0 = bbase + s;

        __syncthreads();
        {
            // fill: 4 shifted copies of 4 rows via register shuffles
            size_t flat = (size_t)(b0 + rr_fill) * NN + 4 * t6;
            const float4* xa = reinterpret_cast<const float4*>(x + flat);
            float4 a = xa[0];
            size_t flatn = flat + 4;
            if (flatn > (size_t)BB * NN - 4) flatn = (size_t)BB * NN - 4;  // clamp OOB
            float4 bq = *reinterpret_cast<const float4*>(x + flatn);

            float* Sr = S + rr_fill * 4 * CS;
            reinterpret_cast<float4*>(Sr + 0 * CS)[t6] = a;
            reinterpret_cast<float4*>(Sr + 1 * CS)[t6] = make_float4(a.y, a.z, a.w, bq.x);
            reinterpret_cast<float4*>(Sr + 2 * CS)[t6] = make_float4(a.z, a.w, bq.x, bq.y);
            reinterpret_cast<float4*>(Sr + 3 * CS)[t6] = make_float4(a.w, bq.x, bq.y, bq.z);
        }
        __syncthreads();

#pragma unroll
        for (int rr = 0; rr < RST; rr++) {
            const float* Sr = S + rr * 4 * CS;
            float* orow = out + (size_t)(b0 + rr) * PP;
#pragma unroll
            for (int g = 0; g < NG; g++) {
                float  xi = Sr[offI[g]];                                     // LDS.32
                float4 xj = *reinterpret_cast<const float4*>(Sr + offA[g]);  // LDS.128
                float4 r4;
                r4.x = xi * xj.x * sp[g][0];
                r4.y = xi * xj.y * sp[g][1];
                r4.z = xi * xj.z * sp[g][2];
                r4.w = xi * xj.w * sp[g][3];
                if (pred[g])                                                 // @P STG.128
                    *reinterpret_cast<float4*>(orow + poff[g]) = r4;
            }
        }
    }
}

// ---------------------------------------------------------------------------
// Cleanup kernel: recompute every group that straddles a row boundary.
// One block.x per row i=1..254; if pstart(i) is not group-aligned, the group
// containing it is a boundary group -> recompute its 4 pairs scalar for all b.
// Duplicate q's (multi-boundary groups) write identical values: benign.
// ---------------------------------------------------------------------------
__global__ void __launch_bounds__(TPB)
cross_utpm_cleanup(const float* __restrict__ x,
                   const float* __restrict__ L,
                   float* __restrict__ out)
{
    int i = blockIdx.x + 1;              // 1..254
    int ps = pstart(i);
    if ((ps & 3) == 0) return;           // boundary is group-aligned: no boundary group

    int p0 = ps & ~3;                    // base pair of the boundary group
    int b  = blockIdx.y * TPB + threadIdx.x;   // grid.y = 16 -> b in [0,4096)

    const float* xr = x + (size_t)b * NN;
    float4 r4;
    float r[4];
#pragma unroll
    for (int k = 0; k < 4; k++) {
        int ik, jk;
        inv_tri(p0 + k, ik, jk);
        float s = 0.0f;
#pragma unroll
        for (int kk = 0; kk < KK; kk++)
            s += L[ik * KK + kk] * L[jk * KK + kk];
        r[k] = xr[ik] * xr[jk] * s;
    }
    r4.x = r[0]; r4.y = r[1]; r4.z = r[2]; r4.w = r[3];
    *reinterpret_cast<float4*>(out + (size_t)b * PP + p0) = r4;
}

extern "C" void kernel_launch(void* const* d_in, const int* in_sizes, int n_in,
                              void* d_out, int out_size)
{
    const float* x = (const float*)d_in[0];        // [4096, 256]
    const float* L = (const float*)d_in[1];        // [256, 16]
    float* out     = (float*)d_out;                // [4096, 32640]

    dim3 gmain(GX, GY);
    cross_utpm_main<<<gmain, TPB>>>(x, L, out);

    dim3 gclean(NN - 2, BB / TPB);                 // (254, 16)
    cross_utpm_cleanup<<<gclean, TPB>>>(x, L, out);
}

// round 11
// speedup vs baseline: 1.5120x; 1.5120x over previous
#include <cuda_runtime.h>
#include <cuda_bf16.h>

// Problem constants (fixed by the reference: B=4096, N=256, K=16)
#define NN    256
#define KK    16
#define PP    32640            // N*(N-1)/2
#define BB    4096
#define TPB   256              // threads per block
#define NG    2                // groups of 4 consecutive pairs per thread
#define TILE  (TPB * NG * 4)   // 2048 pairs per block tile
#define GX    16               // p-tiles: 16*2048 = 32768 >= 32640
#define ROWSB 64               // contiguous batch rows per block
#define GY    (BB / ROWSB)     // 64
#define RST   4                // rows staged per barrier round
#define CS    256              // floats per shift copy
#define CB    16               // rows per cleanup block

// pstart(i) = number of pairs before row i = i*(N-1) - i*(i-1)/2
__host__ __device__ __forceinline__ int pstart(int i) {
    return i * (NN - 1) - (i * (i - 1)) / 2;
}

// invert triangular index p -> (i, j)
__device__ __forceinline__ void inv_tri(int pc, int& io, int& jo) {
    float disc = 2.0f * NN - 1.0f;       // 511
    int i = (int)floorf((disc - sqrtf(disc * disc - 8.0f * (float)pc)) * 0.5f);
    if (i < 0) i = 0;
    if (i > NN - 2) i = NN - 2;
    while (i < NN - 2 && pstart(i + 1) <= pc) i++;
    while (i > 0 && pstart(i) > pc) i--;
    io = i;
    jo = i + 1 + (pc - pstart(i));
}

// ---------------------------------------------------------------------------
// Main kernel. Hot loop is 100% branch-free and predicate-free:
//   per group: 1 LDS.32 (xi, broadcast) + 1 LDS.128 (xj) + FMULs + 1 STG.128.
// Groups that straddle a row boundary store a WRONG float4 (fixed by the
// cleanup kernel below). Out-of-range tail groups are clamped onto the last
// group (PP-4), which is itself a boundary group and thus also rewritten.
// ---------------------------------------------------------------------------
__global__ void __launch_bounds__(TPB)
cross_utpm_main(const float* __restrict__ x,
                const float* __restrict__ L,
                float* __restrict__ out)
{
    // S[row-in-stage][copy r][pos m] = x[b, m + r]; flat: row*4*CS + r*CS + m
    __shared__ __align__(16) float S[RST * 4 * CS];

    const int t     = threadIdx.x;
    const int p0    = blockIdx.x * TILE;
    const int bbase = blockIdx.y * ROWSB;

    // ---- one-time per-thread setup (b-invariant) ----
    int   offA[NG];      // offset (within a row's 4-copy region) of xj LDS.128
    int   offI[NG];      // offset of xi (copy 0)
    int   poff[NG];      // output offset within the p-row (clamped if invalid)
    float sp[NG][4];

#pragma unroll
    for (int g = 0; g < NG; g++) {
        int pg = p0 + (g * TPB + t) * 4;
        bool valid = (pg < PP);
        int base = valid ? pg : 0;           // safe indices for invalid tail
        poff[g] = valid ? pg : (PP - 4);     // clamp onto last (boundary) group

        int i0, j0;
        inv_tri(base, i0, j0);
        offI[g] = i0;                        // copy 0 scalar
        int rA  = j0 & 3;
        offA[g] = rA * CS + (j0 - rA);       // 16B aligned within copy rA

#pragma unroll
        for (int k = 0; k < 4; k++) {
            int i, j;
            inv_tri(base + k, i, j);
            float s = 0.0f;
#pragma unroll
            for (int kk = 0; kk < KK; kk++)
                s += L[i * KK + kk] * L[j * KK + kk];
            sp[g][k] = s;
        }
    }

    // ---- loop over this block's contiguous rows, staged RST at a time ----
    const int t6      = t & 63;      // float4 slot within a row (64 per row)
    const int rr_fill = t >> 6;      // which staged row this thread fills

    for (int s = 0; s < ROWSB; s += RST) {
        int b0 = bbase + s;

        __syncthreads();
        {
            // fill 4 shifted copies of RST rows via register shuffles
            size_t flat = (size_t)(b0 + rr_fill) * NN + 4 * t6;
            float4 a = *reinterpret_cast<const float4*>(x + flat);
            size_t flatn = flat + 4;
            if (flatn > (size_t)BB * NN - 4) flatn = (size_t)BB * NN - 4;
            float4 bq = *reinterpret_cast<const float4*>(x + flatn);

            float* Sr = S + rr_fill * 4 * CS;
            reinterpret_cast<float4*>(Sr + 0 * CS)[t6] = a;
            reinterpret_cast<float4*>(Sr + 1 * CS)[t6] = make_float4(a.y, a.z, a.w, bq.x);
            reinterpret_cast<float4*>(Sr + 2 * CS)[t6] = make_float4(a.z, a.w, bq.x, bq.y);
            reinterpret_cast<float4*>(Sr + 3 * CS)[t6] = make_float4(a.w, bq.x, bq.y, bq.z);
        }
        __syncthreads();

#pragma unroll
        for (int rr = 0; rr < RST; rr++) {
            const float* Sr = S + rr * 4 * CS;
            float* orow = out + (size_t)(b0 + rr) * PP;
#pragma unroll
            for (int g = 0; g < NG; g++) {
                float  xi = Sr[offI[g]];                                     // LDS.32
                float4 xj = *reinterpret_cast<const float4*>(Sr + offA[g]);  // LDS.128
                float4 r4;
                r4.x = xi * xj.x * sp[g][0];
                r4.y = xi * xj.y * sp[g][1];
                r4.z = xi * xj.z * sp[g][2];
                r4.w = xi * xj.w * sp[g][3];
                *reinterpret_cast<float4*>(orow + poff[g]) = r4;             // STG.128
            }
        }
    }
}

// ---------------------------------------------------------------------------
// Cleanup kernel: rewrite every boundary group with correct scalar values.
// Block handles CB contiguous batch rows (staged in shared, coalesced).
// Thread t owns candidate row-split i = t+1; if pstart(i) is not group-
// aligned, its containing group is a boundary group -> rewrite it for all
// CB rows. Groups spanning >2 rows are rewritten by multiple threads with
// byte-identical values (benign, deterministic).
// ---------------------------------------------------------------------------
__global__ void __launch_bounds__(TPB)
cross_utpm_cleanup(const float* __restrict__ x,
                   const float* __restrict__ L,
                   float* __restrict__ out)
{
    __shared__ __align__(16) float xs[CB * NN];   // 16 KB

    const int t     = threadIdx.x;
    const int bbase = blockIdx.x * CB;

    // per-thread boundary-group setup (b-invariant)
    bool  flag = false;
    int   p0 = 0;
    int   ik[4], jk[4];
    float sp[4];

    if (t < NN - 2) {                 // i = t+1 in [1, 254]
        int i  = t + 1;
        int ps = pstart(i);
        flag = (ps & 3) != 0;
        if (flag) {
            p0 = ps & ~3;
#pragma unroll
            for (int k = 0; k < 4; k++) {
                inv_tri(p0 + k, ik[k], jk[k]);
                float s = 0.0f;
#pragma unroll
                for (int kk = 0; kk < KK; kk++)
                    s += L[ik[k] * KK + kk] * L[jk[k] * KK + kk];
                sp[k] = s;
            }
        }
    }

    // stage CB x-rows, coalesced
    {
        const float4* src = reinterpret_cast<const float4*>(x + (size_t)bbase * NN);
        float4* dst = reinterpret_cast<float4*>(xs);
#pragma unroll
        for (int q = 0; q < (CB * NN / 4) / TPB; q++)
            dst[q * TPB + t] = src[q * TPB + t];
    }
    __syncthreads();

    if (flag) {
        for (int r = 0; r < CB; r++) {
            const float* xr = xs + r * NN;
            float4 v;
            v.x = xr[ik[0]] * xr[jk[0]] * sp[0];
            v.y = xr[ik[1]] * xr[jk[1]] * sp[1];
            v.z = xr[ik[2]] * xr[jk[2]] * sp[2];
            v.w = xr[ik[3]] * xr[jk[3]] * sp[3];
            *reinterpret_cast<float4*>(out + (size_t)(bbase + r) * PP + p0) = v;
        }
    }
}

extern "C" void kernel_launch(void* const* d_in, const int* in_sizes, int n_in,
                              void* d_out, int out_size)
{
    const float* x = (const float*)d_in[0];        // [4096, 256]
    const float* L = (const float*)d_in[1];        // [256, 16]
    float* out     = (float*)d_out;                // [4096, 32640]

    dim3 gmain(GX, GY);                            // (16, 64)
    cross_utpm_main<<<gmain, TPB>>>(x, L, out);

    cross_utpm_cleanup<<<BB / CB, TPB>>>(x, L, out);   // 256 blocks, after main
}